// round 8
// baseline (speedup 1.0000x reference)
#include <cuda_runtime.h>
#include <cuda_bf16.h>
#include <mma.h>
#include <cstdint>

using namespace nvcuda;

#define N_NODES   100000
#define N_NODES_P 100032     // multiple of 64
#define N_EDGES_MAX 3200000
#define CH        256        // in == out channels

// ---------------- scratch (static __device__ globals; no allocation) -------
__device__ float g_h[(size_t)N_NODES_P * CH];     // h' = x @ W  (~102.4 MB)
__device__ int   g_deg[N_NODES_P];
__device__ int   g_start[N_NODES_P];
__device__ int   g_cursor[N_NODES_P];
__device__ int   g_sorted_src[N_EDGES_MAX];
__device__ int   g_total;

// ---------------- kernel A: zero degree counters ---------------------------
__global__ void zero_deg_kernel() {
    int i = blockIdx.x * blockDim.x + threadIdx.x;
    if (i < N_NODES_P) g_deg[i] = 0;
    if (i == 0) g_total = 0;
}

// ---------------- kernel B: degree histogram -------------------------------
__global__ __launch_bounds__(256) void hist_kernel(
    const int* __restrict__ dst, int n_edges)
{
    for (int e = blockIdx.x * blockDim.x + threadIdx.x; e < n_edges;
         e += gridDim.x * blockDim.x)
        atomicAdd(&g_deg[dst[e]], 1);     // no return use -> RED
}

// ---------------- kernel C: per-node bucket base (warp-aggregated) ---------
__global__ __launch_bounds__(256) void offsets_kernel(int n_nodes) {
    int i    = blockIdx.x * blockDim.x + threadIdx.x;
    int lane = threadIdx.x & 31;
    int d    = (i < n_nodes) ? g_deg[i] : 0;

    int incl = d;
#pragma unroll
    for (int o = 1; o < 32; o <<= 1) {
        int t = __shfl_up_sync(0xffffffffu, incl, o);
        if (lane >= o) incl += t;
    }
    int total = __shfl_sync(0xffffffffu, incl, 31);
    int base  = 0;
    if (lane == 31) base = atomicAdd(&g_total, total);
    base = __shfl_sync(0xffffffffu, base, 31);

    if (i < n_nodes) {
        int st = base + incl - d;
        g_start[i]  = st;
        g_cursor[i] = st;
    }
}

// ---------------- kernel D: bucket edges by dst ----------------------------
__global__ __launch_bounds__(256) void bucket_kernel(
    const int* __restrict__ src, const int* __restrict__ dst, int n_edges)
{
    for (int e = blockIdx.x * blockDim.x + threadIdx.x; e < n_edges;
         e += gridDim.x * blockDim.x) {
        int d = dst[e];
        int s = src[e];                       // overlap load with ATOMG
        int pos = atomicAdd(&g_cursor[d], 1);
        g_sorted_src[pos] = s;
    }
}

// ---------------- kernel E: h' = x @ W (split-bf16 tensor cores) -----------
// Block: 64 rows x 256 cols, 256 threads = 8 warps.
// Warp (wm in [0,4), wn in [0,2)): tile m16 x n128 = 8 wmma frags.
// Split: v = hi + lo (bf16 each); acc += Ah*Bh + Ah*Bl + Al*Bh (err ~1e-5).
__global__ __launch_bounds__(256) void gemm_h_kernel(
    const float* __restrict__ x,      // [n_nodes, 256]
    const float* __restrict__ W,      // [256, 256] row-major
    int n_nodes)
{
    __shared__ __align__(32) __nv_bfloat16 axh[64][16];
    __shared__ __align__(32) __nv_bfloat16 axl[64][16];
    __shared__ __align__(32) __nv_bfloat16 bwh[16][256];
    __shared__ __align__(32) __nv_bfloat16 bwl[16][256];

    const int tid  = threadIdx.x;
    const int warp = tid >> 5;
    const int wm   = warp >> 1;     // 0..3 (row tile)
    const int wn   = warp & 1;      // 0..1 (col half)
    const int row0 = blockIdx.x * 64;

    wmma::fragment<wmma::accumulator, 16, 16, 16, float> acc[8];
#pragma unroll
    for (int i = 0; i < 8; i++) wmma::fill_fragment(acc[i], 0.0f);

    for (int kk = 0; kk < 16; kk++) {            // 16 k-steps of 16
        // --- x tile 64x16: one float4 per thread ---
        {
            int r  = tid >> 2;                   // 0..63
            int c4 = tid & 3;                    // 0..3
            int grow = row0 + r;
            float4 v = make_float4(0.f, 0.f, 0.f, 0.f);
            if (grow < n_nodes)
                v = *reinterpret_cast<const float4*>(
                    x + (size_t)grow * CH + kk * 16 + c4 * 4);
            const float* pv = &v.x;
#pragma unroll
            for (int i = 0; i < 4; i++) {
                __nv_bfloat16 hi = __float2bfloat16(pv[i]);
                __nv_bfloat16 lo = __float2bfloat16(pv[i] - __bfloat162float(hi));
                axh[r][c4 * 4 + i] = hi;
                axl[r][c4 * 4 + i] = lo;
            }
        }
        // --- W tile 16x256: 4 float4 per thread ---
#pragma unroll
        for (int it = 0; it < 4; it++) {
            int id = tid + it * 256;
            int r  = id >> 6;                    // 0..15
            int c4 = id & 63;                    // 0..63
            float4 v = *reinterpret_cast<const float4*>(
                W + (size_t)(kk * 16 + r) * CH + c4 * 4);
            const float* pv = &v.x;
#pragma unroll
            for (int i = 0; i < 4; i++) {
                __nv_bfloat16 hi = __float2bfloat16(pv[i]);
                __nv_bfloat16 lo = __float2bfloat16(pv[i] - __bfloat162float(hi));
                bwh[r][c4 * 4 + i] = hi;
                bwl[r][c4 * 4 + i] = lo;
            }
        }
        __syncthreads();

        wmma::fragment<wmma::matrix_a, 16, 16, 16, __nv_bfloat16, wmma::row_major> Ah, Al;
        wmma::load_matrix_sync(Ah, &axh[wm * 16][0], 16);
        wmma::load_matrix_sync(Al, &axl[wm * 16][0], 16);

#pragma unroll
        for (int nf = 0; nf < 8; nf++) {
            wmma::fragment<wmma::matrix_b, 16, 16, 16, __nv_bfloat16, wmma::row_major> Bh, Bl;
            int col = wn * 128 + nf * 16;
            wmma::load_matrix_sync(Bh, &bwh[0][col], 256);
            wmma::load_matrix_sync(Bl, &bwl[0][col], 256);
            wmma::mma_sync(acc[nf], Ah, Bh, acc[nf]);
            wmma::mma_sync(acc[nf], Ah, Bl, acc[nf]);
            wmma::mma_sync(acc[nf], Al, Bh, acc[nf]);
        }
        __syncthreads();
    }

    // store h' (padded scratch: rows >= n_nodes hold zeros-from-zero-A; unused)
#pragma unroll
    for (int nf = 0; nf < 8; nf++) {
        int col = wn * 128 + nf * 16;
        wmma::store_matrix_sync(
            g_h + (size_t)(row0 + wm * 16) * CH + col,
            acc[nf], CH, wmma::mem_row_major);
    }
}

// ---------------- kernel F: out[d] = (sum h'[src] + deg*b)/max(deg,1) ------
// One warp per dst node; lane holds float4 columns {lane, lane+32}.
__global__ __launch_bounds__(256) void aggregate_kernel(
    const float* __restrict__ bias,
    float* __restrict__ out, int n_nodes)
{
    const int warp = (blockIdx.x * blockDim.x + threadIdx.x) >> 5;
    const int lane = threadIdx.x & 31;
    if (warp >= n_nodes) return;

    const int beg = g_start[warp];
    const int cnt = g_deg[warp];

    float4 a0 = make_float4(0.f, 0.f, 0.f, 0.f);
    float4 a1 = make_float4(0.f, 0.f, 0.f, 0.f);

    for (int j0 = 0; j0 < cnt; j0 += 32) {
        int idx = 0;
        if (j0 + lane < cnt) idx = g_sorted_src[beg + j0 + lane];
        const int m = min(32, cnt - j0);
        for (int j = 0; j < m; j++) {
            int s = __shfl_sync(0xffffffffu, idx, j);
            const float4* hr = reinterpret_cast<const float4*>(g_h + (size_t)s * CH);
            float4 v0 = __ldg(hr + lane);
            float4 v1 = __ldg(hr + lane + 32);
            a0.x += v0.x; a0.y += v0.y; a0.z += v0.z; a0.w += v0.w;
            a1.x += v1.x; a1.y += v1.y; a1.z += v1.z; a1.w += v1.w;
        }
    }

    const float4 b0 = reinterpret_cast<const float4*>(bias)[lane];
    const float4 b1 = reinterpret_cast<const float4*>(bias)[lane + 32];
    const float cf    = (float)cnt;
    const float scale = 1.0f / fmaxf(cf, 1.0f);

    float4 o0, o1;
    o0.x = (a0.x + cf * b0.x) * scale; o0.y = (a0.y + cf * b0.y) * scale;
    o0.z = (a0.z + cf * b0.z) * scale; o0.w = (a0.w + cf * b0.w) * scale;
    o1.x = (a1.x + cf * b1.x) * scale; o1.y = (a1.y + cf * b1.y) * scale;
    o1.z = (a1.z + cf * b1.z) * scale; o1.w = (a1.w + cf * b1.w) * scale;

    float4* orow = reinterpret_cast<float4*>(out + (size_t)warp * CH);
    orow[lane]      = o0;
    orow[lane + 32] = o1;
}

// ---------------- launch ---------------------------------------------------
extern "C" void kernel_launch(void* const* d_in, const int* in_sizes, int n_in,
                              void* d_out, int out_size)
{
    const float* x    = (const float*)d_in[0];
    const int*   src  = (const int*)d_in[1];
    const int*   dst  = (const int*)d_in[2];
    const float* W    = (const float*)d_in[3];
    const float* bias = (const float*)d_in[4];
    float*       out  = (float*)d_out;

    const int n_nodes = in_sizes[0] / CH;
    const int n_edges = in_sizes[1];

    zero_deg_kernel<<<(N_NODES_P + 255) / 256, 256>>>();
    hist_kernel<<<1184, 256>>>(dst, n_edges);
    offsets_kernel<<<(n_nodes + 255) / 256, 256>>>(n_nodes);
    bucket_kernel<<<1184, 256>>>(src, dst, n_edges);
    gemm_h_kernel<<<(n_nodes + 63) / 64, 256>>>(x, W, n_nodes);
    aggregate_kernel<<<(n_nodes * 32 + 255) / 256, 256>>>(bias, out, n_nodes);
}